// round 12
// baseline (speedup 1.0000x reference)
#include <cuda_runtime.h>

// Retina glimpse: x [B=16384, C=3, 32, 32] f32, l [B,2] f32 in [-1,1].
// Outputs concatenated into d_out:
//   full  [B,3,32,32] : x masked to the valid part of the 16x16 window, else 0
//   patch [B,3,16,16] : gathered window, 0 where out of [0,32) bounds
//
// This round: sm_100 256-bit ld/st (.v8.f32) for the full stream + warp
// specialization (warps 0-5: full, warps 6-7: patch) so the two output
// streams overlap.

#define BB 16384
#define CC 3
#define HH 32
#define GG 16
#define FULL_PER_B (CC*HH*HH)   // 3072 floats = 384 float8
#define PATCH_PER_B (CC*GG*GG)  // 768 floats  = 192 float4

struct __align__(32) f8 { float v[8]; };

__device__ __forceinline__ void ldg_nc_v8(f8& d, const float* p) {
    asm volatile("ld.global.nc.v8.f32 {%0,%1,%2,%3,%4,%5,%6,%7}, [%8];"
        : "=f"(d.v[0]), "=f"(d.v[1]), "=f"(d.v[2]), "=f"(d.v[3]),
          "=f"(d.v[4]), "=f"(d.v[5]), "=f"(d.v[6]), "=f"(d.v[7])
        : "l"(p));
}
__device__ __forceinline__ void stg_cs_v8(float* p, const f8& d) {
    asm volatile("st.global.cs.v8.f32 [%0], {%1,%2,%3,%4,%5,%6,%7,%8};"
        :: "l"(p),
           "f"(d.v[0]), "f"(d.v[1]), "f"(d.v[2]), "f"(d.v[3]),
           "f"(d.v[4]), "f"(d.v[5]), "f"(d.v[6]), "f"(d.v[7])
        : "memory");
}

__global__ __launch_bounds__(256) void retina_kernel(
    const float* __restrict__ x,
    const float* __restrict__ l,
    float* __restrict__ full,
    float* __restrict__ patch)
{
    const int b = blockIdx.x;
    const int tid = threadIdx.x;

    // Window corner (per-thread; l loads are same-line L1 broadcasts).
    float l0 = fminf(fmaxf(__ldg(&l[2 * b + 0]), -1.0f), 1.0f);
    float l1 = fminf(fmaxf(__ldg(&l[2 * b + 1]), -1.0f), 1.0f);
    const int rs = (int)(0.5f * ((l0 + 1.0f) * 32.0f)) - GG / 2;  // [-8,24]
    const int cs = (int)(0.5f * ((l1 + 1.0f) * 32.0f)) - GG / 2;

    const float* xb = x + (size_t)b * FULL_PER_B;

    if (tid < 192) {
        // ---- FULL stream: 384 float8/sample, 2 per thread (warps 0-5) ----
        float* fb = full + (size_t)b * FULL_PER_B;
        f8 xv[2];
        int  w0a[2], offs[2];
        bool ov[2];
        #pragma unroll
        for (int it = 0; it < 2; ++it) {
            int u = it * 192 + tid;         // [0,384) float8 index
            int ch  = u >> 7;               // 128 float8 per channel
            int rem = u & 127;
            int h   = rem >> 2;             // 4 float8 per 32-col row
            int w0  = (rem & 3) << 3;       // first column of this float8
            w0a[it]  = w0;
            offs[it] = (ch << 10) + (h << 5) + w0;
            ov[it] = (h >= rs) && (h < rs + GG) &&
                     (w0 + 7 >= cs) && (w0 <= cs + GG - 1);
            #pragma unroll
            for (int k = 0; k < 8; ++k) xv[it].v[k] = 0.f;
            if (ov[it])
                ldg_nc_v8(xv[it], xb + offs[it]);
        }
        #pragma unroll
        for (int it = 0; it < 2; ++it) {
            int u = it * 192 + tid;
            int w0 = w0a[it];
            f8 out;
            #pragma unroll
            for (int k = 0; k < 8; ++k) {
                int c = w0 + k;
                out.v[k] = (ov[it] && c >= cs && c < cs + GG) ? xv[it].v[k] : 0.f;
            }
            stg_cs_v8(fb + ((size_t)u << 3), out);
        }
    } else {
        // ---- PATCH stream: 192 float4/sample, 3 per thread (warps 6-7) ----
        float* pb = patch + (size_t)b * PATCH_PER_B;
        const int t = tid - 192;            // [0,64)
        #pragma unroll
        for (int it = 0; it < 3; ++it) {
            int e4  = it * 64 + t;          // [0,192)
            int ch  = e4 >> 6;              // 64 float4 per channel
            int rem = e4 & 63;
            int i   = rem >> 2;             // patch row [0,16)
            int j0  = (rem & 3) << 2;       // first patch col of this float4
            int row = rs + i;
            float4 out = make_float4(0.f, 0.f, 0.f, 0.f);
            if (row >= 0 && row < HH) {
                const float* xr = xb + (ch << 10) + (row << 5);
                int c0 = cs + j0;
                if (c0 + 0 >= 0 && c0 + 0 < HH) out.x = __ldg(xr + c0 + 0);
                if (c0 + 1 >= 0 && c0 + 1 < HH) out.y = __ldg(xr + c0 + 1);
                if (c0 + 2 >= 0 && c0 + 2 < HH) out.z = __ldg(xr + c0 + 2);
                if (c0 + 3 >= 0 && c0 + 3 < HH) out.w = __ldg(xr + c0 + 3);
            }
            __stcs((float4*)(pb + ((size_t)e4 << 2)), out);
        }
    }
}

extern "C" void kernel_launch(void* const* d_in, const int* in_sizes, int n_in,
                              void* d_out, int out_size)
{
    const float* x = (const float*)d_in[0];   // [16384,3,32,32]
    const float* l = (const float*)d_in[1];   // [16384,2]
    float* full  = (float*)d_out;
    float* patch = (float*)d_out + (size_t)BB * FULL_PER_B;
    retina_kernel<<<BB, 256>>>(x, l, full, patch);
}